// round 4
// baseline (speedup 1.0000x reference)
#include <cuda_runtime.h>
#include <cuda_bf16.h>
#include <cstdint>

using bf16 = __nv_bfloat16;

constexpr int KDIM = 4096;
constexpr size_t SZ_W = (size_t)4096 * 4096;
constexpr size_t SZ_X = (size_t)8192 * 4096;

// ---------------- static device scratch ----------------
__device__ bf16 g_Ut_hi[SZ_W], g_Ut_lo[SZ_W];   // Ut[o,a] = U[a,o]
__device__ bf16 g_Vt_hi[SZ_W], g_Vt_lo[SZ_W];   // Vt[i,b] = V[b,i]
__device__ bf16 g_qbf[SZ_W];                    // q[b,a] as bf16 (exact)
__device__ bf16 g_x_hi[SZ_X], g_x_lo[SZ_X];     // x[m,i]
__device__ bf16 g_T1_hi[SZ_W], g_T1_lo[SZ_W];   // T[o,b] hi/lo
__device__ bf16 g_W_hi[SZ_W],  g_W_lo[SZ_W];    // Wtt[o,i] hi/lo
__device__ float g_colsum[4096];                // colsum_a U[a,o]

// ---------------- PTX helpers (baseline ISA only) ----------------
__device__ __forceinline__ uint32_t smem_u32(const void* p) {
    uint32_t a;
    asm("{ .reg .u64 t; cvta.to.shared.u64 t, %1; cvt.u32.u64 %0, t; }" : "=r"(a) : "l"(p));
    return a;
}
__device__ __forceinline__ void cp16(uint32_t dst, const void* src) {
    asm volatile("cp.async.cg.shared.global [%0], [%1], 16;" :: "r"(dst), "l"(src));
}
__device__ __forceinline__ void ldsm4(uint32_t* r, uint32_t addr) {
    asm volatile("ldmatrix.sync.aligned.m8n8.x4.shared.b16 {%0,%1,%2,%3}, [%4];"
                 : "=r"(r[0]), "=r"(r[1]), "=r"(r[2]), "=r"(r[3]) : "r"(addr));
}
__device__ __forceinline__ void mma16816(float* c, const uint32_t* a, const uint32_t* b) {
    asm volatile("mma.sync.aligned.m16n8k16.row.col.f32.bf16.bf16.f32 "
                 "{%0,%1,%2,%3}, {%4,%5,%6,%7}, {%8,%9}, {%0,%1,%2,%3};"
                 : "+f"(c[0]), "+f"(c[1]), "+f"(c[2]), "+f"(c[3])
                 : "r"(a[0]), "r"(a[1]), "r"(a[2]), "r"(a[3]), "r"(b[0]), "r"(b[1]));
}
__device__ __forceinline__ uint32_t sw64(uint32_t o) { return o ^ ((o >> 3) & 0x30); }

// ---------------- preprocessing ----------------
template <int WHICH>  // 0: U -> g_Ut, 1: V -> g_Vt  (transpose + hi/lo split)
__global__ void transconv(const float* __restrict__ src) {
    bf16* dhi = (WHICH == 0) ? g_Ut_hi : g_Vt_hi;
    bf16* dlo = (WHICH == 0) ? g_Ut_lo : g_Vt_lo;
    __shared__ float t[32][33];
    int c0 = blockIdx.x * 32, r0 = blockIdx.y * 32;
    int tx = threadIdx.x, ty = threadIdx.y;
#pragma unroll
    for (int j = 0; j < 4; j++)
        t[ty + j * 8][tx] = src[(size_t)(r0 + ty + j * 8) * 4096 + c0 + tx];
    __syncthreads();
#pragma unroll
    for (int j = 0; j < 4; j++) {
        int c = c0 + ty + j * 8;
        float v = t[tx][ty + j * 8];
        bf16 h = __float2bfloat16(v);
        dhi[(size_t)c * 4096 + r0 + tx] = h;
        dlo[(size_t)c * 4096 + r0 + tx] = __float2bfloat16(v - __bfloat162float(h));
    }
}

__global__ void convx(const float* __restrict__ xin) {  // x -> hi/lo
    size_t i = (size_t)blockIdx.x * 256 + threadIdx.x;
    float4 v = ((const float4*)xin)[i];
    union { bf16 b[4]; uint2 u; } H, L;
    float f[4] = {v.x, v.y, v.z, v.w};
#pragma unroll
    for (int j = 0; j < 4; j++) {
        bf16 h = __float2bfloat16(f[j]);
        H.b[j] = h;
        L.b[j] = __float2bfloat16(f[j] - __bfloat162float(h));
    }
    ((uint2*)g_x_hi)[i] = H.u;
    ((uint2*)g_x_lo)[i] = L.u;
}

__global__ void convq(const int* __restrict__ q) {
    size_t i = (size_t)blockIdx.x * 256 + threadIdx.x;
    int4 v = ((const int4*)q)[i];
    union { bf16 b[4]; uint2 u; } H;
    H.b[0] = __float2bfloat16((float)v.x);
    H.b[1] = __float2bfloat16((float)v.y);
    H.b[2] = __float2bfloat16((float)v.z);
    H.b[3] = __float2bfloat16((float)v.w);
    ((uint2*)g_qbf)[i] = H.u;
}

__global__ void colsum(const float* __restrict__ U) {
    int col = blockIdx.x * 128 + threadIdx.x;
    float s = 0.f;
    for (int k = 0; k < 4096; k++) s += U[(size_t)k * 4096 + col];
    g_colsum[col] = s;
}

// ---------------- HMMA GEMM (mma.sync m16n8k16 bf16) ----------------
// C[M,N] = sum_k A[m,k]*B[n,k]  (both K-major), split-precision products.
// MODE 0: A=Ut hi/lo, B=qbf (exact).   epi: v*dq_mul - dq_sub*colsum[row]; emit hi/lo -> g_T1
// MODE 1: A=T1 hi/lo, B=Vt hi/lo.      epi: v / scaleWH[col];              emit hi/lo -> g_W
// MODE 2: A=x  hi/lo, B=W  hi/lo.      epi: v + bias[col];                 emit fp32 -> out
constexpr int BM = 128, BN = 256, BK = 32, STAGES = 3, NCHUNK = KDIM / BK;
constexpr uint32_t TILE_A = 128 * 64;          // 8 KB  (BM rows x 64B)
constexpr uint32_t TILE_B = 256 * 64;          // 16 KB (BN rows x 64B)
constexpr uint32_t OFF_AH = 0;
constexpr uint32_t OFF_AL = TILE_A;
constexpr uint32_t OFF_BH = 2 * TILE_A;
constexpr uint32_t OFF_BL = 2 * TILE_A + TILE_B;
constexpr uint32_t STAGE_B = 2 * TILE_A + 2 * TILE_B;   // 48 KB
constexpr uint32_t SMEM_SZ = STAGES * STAGE_B + 1024;

template <int MODE>
__global__ __launch_bounds__(512, 1) void hgemm(const float* __restrict__ aux,
                                                float* __restrict__ outp) {
    constexpr bool HAS_BL = (MODE != 0);
    const bf16 *Ahi, *Alo, *Bhi, *Blo = nullptr;
    if (MODE == 0) { Ahi = g_Ut_hi; Alo = g_Ut_lo; Bhi = g_qbf; }
    if (MODE == 1) { Ahi = g_T1_hi; Alo = g_T1_lo; Bhi = g_Vt_hi; Blo = g_Vt_lo; }
    if (MODE == 2) { Ahi = g_x_hi;  Alo = g_x_lo;  Bhi = g_W_hi;  Blo = g_W_lo; }

    extern __shared__ char dsm[];
    const uint32_t sbase = (smem_u32(dsm) + 1023u) & ~1023u;

    const int tid = threadIdx.x;
    const int wid = tid >> 5, lane = tid & 31;
    const int warp_m = wid >> 3;         // 0..1  (64 rows each)
    const int warp_n = wid & 7;          // 0..7  (32 cols each)
    const int m0 = blockIdx.y * BM, n0 = blockIdx.x * BN;

    float acc[4][4][4];
#pragma unroll
    for (int a = 0; a < 4; a++)
#pragma unroll
        for (int b = 0; b < 4; b++)
#pragma unroll
            for (int d = 0; d < 4; d++) acc[a][b][d] = 0.f;

    // loader: A = 512 cp16 slots (hi+lo), B = 1024 slots (hi[+lo])
    auto load_stage = [&](int s, int c) {
        const uint32_t sb = sbase + (uint32_t)s * STAGE_B;
        const int k0 = c * BK;
        {
            int r = tid >> 2, cc = tid & 3;
            uint32_t sw = sw64((uint32_t)(r * 64 + cc * 16));
            size_t gA = (size_t)(m0 + r) * KDIM + k0 + cc * 8;
            cp16(sb + OFF_AH + sw, Ahi + gA);
            cp16(sb + OFF_AL + sw, Alo + gA);
        }
#pragma unroll
        for (int t = 0; t < 2; t++) {
            int idx = tid + t * 512;
            int r = idx >> 2, cc = idx & 3;
            uint32_t sw = sw64((uint32_t)(r * 64 + cc * 16));
            size_t gB = (size_t)(n0 + r) * KDIM + k0 + cc * 8;
            cp16(sb + OFF_BH + sw, Bhi + gB);
            if (HAS_BL) cp16(sb + OFF_BL + sw, Blo + gB);
        }
        asm volatile("cp.async.commit_group;");
    };

    load_stage(0, 0);
    load_stage(1, 1);

    const uint32_t a_row = (uint32_t)(warp_m * 64 + (lane & 15));
    const uint32_t a_kb  = (uint32_t)((lane >> 4) << 4);
    const uint32_t b_row = (uint32_t)(warp_n * 32 + ((lane >> 4) << 3) + (lane & 7));
    const uint32_t b_kb  = (uint32_t)(((lane >> 3) & 1) << 4);

    for (int c = 0; c < NCHUNK; c++) {
        asm volatile("cp.async.wait_group 1;");
        __syncthreads();
        if (c + 2 < NCHUNK) load_stage((c + 2) % 3, c + 2);
        else asm volatile("cp.async.commit_group;");

        const uint32_t sb = sbase + (uint32_t)(c % 3) * STAGE_B;
#pragma unroll
        for (int ks = 0; ks < 2; ks++) {
            uint32_t ah[4][4], al[4][4], bh[4][2], bl[4][2];
#pragma unroll
            for (int mt = 0; mt < 4; mt++) {
                uint32_t o = sw64((a_row + mt * 16) * 64 + ks * 32 + a_kb);
                ldsm4(ah[mt], sb + OFF_AH + o);
                ldsm4(al[mt], sb + OFF_AL + o);
            }
#pragma unroll
            for (int np = 0; np < 2; np++) {
                uint32_t o = sw64((b_row + np * 16) * 64 + ks * 32 + b_kb);
                uint32_t tmp[4];
                ldsm4(tmp, sb + OFF_BH + o);
                bh[2 * np][0] = tmp[0]; bh[2 * np][1] = tmp[1];
                bh[2 * np + 1][0] = tmp[2]; bh[2 * np + 1][1] = tmp[3];
                if (HAS_BL) {
                    ldsm4(tmp, sb + OFF_BL + o);
                    bl[2 * np][0] = tmp[0]; bl[2 * np][1] = tmp[1];
                    bl[2 * np + 1][0] = tmp[2]; bl[2 * np + 1][1] = tmp[3];
                }
            }
#pragma unroll
            for (int mt = 0; mt < 4; mt++)
#pragma unroll
                for (int nt = 0; nt < 4; nt++) {
                    mma16816(acc[mt][nt], ah[mt], bh[nt]);
                    if (HAS_BL) mma16816(acc[mt][nt], ah[mt], bl[nt]);
                    mma16816(acc[mt][nt], al[mt], bh[nt]);
                }
        }
    }

    // ---------------- epilogue ----------------
    const int gid = lane >> 2, tig = lane & 3;
    float dq_mul = 0.f, dq_sub = 0.f;
    if (MODE == 0) { float sc = aux[0]; dq_mul = sc * (2.0f / 15.0f); dq_sub = sc; }

    float c0f[4], c1f[4];
#pragma unroll
    for (int nt = 0; nt < 4; nt++) {
        int col = n0 + warp_n * 32 + nt * 8 + tig * 2;
        if (MODE == 1) { c0f[nt] = 1.0f / aux[col]; c1f[nt] = 1.0f / aux[col + 1]; }
        else if (MODE == 2) { c0f[nt] = aux[col]; c1f[nt] = aux[col + 1]; }
        else { c0f[nt] = 0.f; c1f[nt] = 0.f; }
    }

#pragma unroll
    for (int mt = 0; mt < 4; mt++) {
        int r0 = m0 + warp_m * 64 + mt * 16 + gid;
        int r1 = r0 + 8;
        float sub0 = 0.f, sub1 = 0.f;
        if (MODE == 0) { sub0 = dq_sub * g_colsum[r0]; sub1 = dq_sub * g_colsum[r1]; }
#pragma unroll
        for (int nt = 0; nt < 4; nt++) {
            int col = n0 + warp_n * 32 + nt * 8 + tig * 2;
            float v0 = acc[mt][nt][0], v1 = acc[mt][nt][1];
            float v2 = acc[mt][nt][2], v3 = acc[mt][nt][3];
            if (MODE == 0) {
                v0 = v0 * dq_mul - sub0; v1 = v1 * dq_mul - sub0;
                v2 = v2 * dq_mul - sub1; v3 = v3 * dq_mul - sub1;
            } else if (MODE == 1) {
                v0 *= c0f[nt]; v1 *= c1f[nt]; v2 *= c0f[nt]; v3 *= c1f[nt];
            } else {
                v0 += c0f[nt]; v1 += c1f[nt]; v2 += c0f[nt]; v3 += c1f[nt];
            }
            if (MODE == 2) {
                *(float2*)(outp + (size_t)r0 * 4096 + col) = make_float2(v0, v1);
                *(float2*)(outp + (size_t)r1 * 4096 + col) = make_float2(v2, v3);
            } else {
                bf16* Chi = (MODE == 0) ? g_T1_hi : g_W_hi;
                bf16* Clo = (MODE == 0) ? g_T1_lo : g_W_lo;
                union { bf16 b[2]; uint32_t u; } h, l;
                h.b[0] = __float2bfloat16(v0);
                l.b[0] = __float2bfloat16(v0 - __bfloat162float(h.b[0]));
                h.b[1] = __float2bfloat16(v1);
                l.b[1] = __float2bfloat16(v1 - __bfloat162float(h.b[1]));
                *(uint32_t*)(Chi + (size_t)r0 * 4096 + col) = h.u;
                *(uint32_t*)(Clo + (size_t)r0 * 4096 + col) = l.u;
                h.b[0] = __float2bfloat16(v2);
                l.b[0] = __float2bfloat16(v2 - __bfloat162float(h.b[0]));
                h.b[1] = __float2bfloat16(v3);
                l.b[1] = __float2bfloat16(v3 - __bfloat162float(h.b[1]));
                *(uint32_t*)(Chi + (size_t)r1 * 4096 + col) = h.u;
                *(uint32_t*)(Clo + (size_t)r1 * 4096 + col) = l.u;
            }
        }
    }
}

// ---------------- host ----------------
extern "C" void kernel_launch(void* const* d_in, const int* in_sizes, int n_in,
                              void* d_out, int out_size) {
    const float* x       = (const float*)d_in[0];
    const int*   qweight = (const int*)  d_in[1];
    const float* scale   = (const float*)d_in[2];
    const float* scaleWH = (const float*)d_in[3];
    const float* bias    = (const float*)d_in[4];
    const float* U       = (const float*)d_in[5];
    const float* V       = (const float*)d_in[6];
    float*       out     = (float*)d_out;

    cudaFuncSetAttribute(hgemm<0>, cudaFuncAttributeMaxDynamicSharedMemorySize, SMEM_SZ);
    cudaFuncSetAttribute(hgemm<1>, cudaFuncAttributeMaxDynamicSharedMemorySize, SMEM_SZ);
    cudaFuncSetAttribute(hgemm<2>, cudaFuncAttributeMaxDynamicSharedMemorySize, SMEM_SZ);

    dim3 tb32(32, 8);
    // order chosen so hgemm<0> is 0-based launch #3 (the slot ncu captures)
    convq<<<16384, 256>>>(qweight);                 // 0
    transconv<0><<<dim3(128, 128), tb32>>>(U);      // 1
    colsum<<<32, 128>>>(U);                         // 2
    hgemm<0><<<dim3(16, 32), 512, SMEM_SZ>>>(scale, nullptr);    // 3  <- profiled
    transconv<1><<<dim3(128, 128), tb32>>>(V);      // 4
    hgemm<1><<<dim3(16, 32), 512, SMEM_SZ>>>(scaleWH, nullptr);  // 5
    convx<<<(unsigned)(SZ_X / 4 / 256), 256>>>(x);  // 6
    hgemm<2><<<dim3(16, 64), 512, SMEM_SZ>>>(bias, out);         // 7
}

// round 5
// speedup vs baseline: 1.1834x; 1.1834x over previous
#include <cuda_runtime.h>
#include <cuda_bf16.h>
#include <cstdint>

using bf16 = __nv_bfloat16;

constexpr int KDIM = 4096;
constexpr size_t SZ_W = (size_t)4096 * 4096;
constexpr size_t SZ_X = (size_t)8192 * 4096;

// ---------------- static device scratch ----------------
__device__ bf16 g_Ut_hi[SZ_W], g_Ut_lo[SZ_W];   // Ut[o,a] = U[a,o]
__device__ bf16 g_Vt_hi[SZ_W], g_Vt_lo[SZ_W];   // Vt[i,b] = V[b,i]
__device__ bf16 g_qbf[SZ_W];                    // q[b,a] as bf16 (exact)
__device__ bf16 g_x_hi[SZ_X], g_x_lo[SZ_X];     // x[m,i]
__device__ bf16 g_T1_hi[SZ_W], g_T1_lo[SZ_W];   // T[o,b] hi/lo
__device__ bf16 g_W_hi[SZ_W],  g_W_lo[SZ_W];    // Wtt[o,i] hi/lo
__device__ float g_cs_part[8 * 4096];           // partial colsums of U

// ---------------- PTX helpers ----------------
__device__ __forceinline__ uint32_t smem_u32(const void* p) {
    uint32_t a;
    asm("{ .reg .u64 t; cvta.to.shared.u64 t, %1; cvt.u32.u64 %0, t; }" : "=r"(a) : "l"(p));
    return a;
}
__device__ __forceinline__ void cp16(uint32_t dst, const void* src) {
    asm volatile("cp.async.cg.shared.global [%0], [%1], 16;" :: "r"(dst), "l"(src));
}
__device__ __forceinline__ void ldsm4(uint32_t* r, uint32_t addr) {
    asm volatile("ldmatrix.sync.aligned.m8n8.x4.shared.b16 {%0,%1,%2,%3}, [%4];"
                 : "=r"(r[0]), "=r"(r[1]), "=r"(r[2]), "=r"(r[3]) : "r"(addr));
}
__device__ __forceinline__ void mma16816(float* c, const uint32_t* a, const uint32_t* b) {
    asm volatile("mma.sync.aligned.m16n8k16.row.col.f32.bf16.bf16.f32 "
                 "{%0,%1,%2,%3}, {%4,%5,%6,%7}, {%8,%9}, {%0,%1,%2,%3};"
                 : "+f"(c[0]), "+f"(c[1]), "+f"(c[2]), "+f"(c[3])
                 : "r"(a[0]), "r"(a[1]), "r"(a[2]), "r"(a[3]), "r"(b[0]), "r"(b[1]));
}
__device__ __forceinline__ uint32_t sw128(uint32_t o) { return o ^ ((o >> 3) & 0x70); }

// ---------------- preprocessing ----------------
template <int WHICH>  // 0: U -> g_Ut, 1: V -> g_Vt  (transpose + hi/lo split)
__global__ void transconv(const float* __restrict__ src) {
    bf16* dhi = (WHICH == 0) ? g_Ut_hi : g_Vt_hi;
    bf16* dlo = (WHICH == 0) ? g_Ut_lo : g_Vt_lo;
    __shared__ float t[32][33];
    int c0 = blockIdx.x * 32, r0 = blockIdx.y * 32;
    int tx = threadIdx.x, ty = threadIdx.y;
#pragma unroll
    for (int j = 0; j < 4; j++)
        t[ty + j * 8][tx] = src[(size_t)(r0 + ty + j * 8) * 4096 + c0 + tx];
    __syncthreads();
#pragma unroll
    for (int j = 0; j < 4; j++) {
        int c = c0 + ty + j * 8;
        float v = t[tx][ty + j * 8];
        bf16 h = __float2bfloat16(v);
        dhi[(size_t)c * 4096 + r0 + tx] = h;
        dlo[(size_t)c * 4096 + r0 + tx] = __float2bfloat16(v - __bfloat162float(h));
    }
}

__global__ void convx(const float* __restrict__ xin) {
    size_t i = (size_t)blockIdx.x * 256 + threadIdx.x;
    float4 v = ((const float4*)xin)[i];
    union { bf16 b[4]; uint2 u; } H, L;
    float f[4] = {v.x, v.y, v.z, v.w};
#pragma unroll
    for (int j = 0; j < 4; j++) {
        bf16 h = __float2bfloat16(f[j]);
        H.b[j] = h;
        L.b[j] = __float2bfloat16(f[j] - __bfloat162float(h));
    }
    ((uint2*)g_x_hi)[i] = H.u;
    ((uint2*)g_x_lo)[i] = L.u;
}

__global__ void convq(const int* __restrict__ q) {
    size_t i = (size_t)blockIdx.x * 256 + threadIdx.x;
    int4 v = ((const int4*)q)[i];
    union { bf16 b[4]; uint2 u; } H;
    H.b[0] = __float2bfloat16((float)v.x);
    H.b[1] = __float2bfloat16((float)v.y);
    H.b[2] = __float2bfloat16((float)v.z);
    H.b[3] = __float2bfloat16((float)v.w);
    ((uint2*)g_qbf)[i] = H.u;
}

__global__ void colsum_part(const float* __restrict__ U) {
    int col = blockIdx.x * 256 + threadIdx.x;
    int seg = blockIdx.y;
    float s = 0.f;
    for (int k = seg * 512; k < seg * 512 + 512; k++)
        s += U[(size_t)k * 4096 + col];
    g_cs_part[seg * 4096 + col] = s;
}

// ---------------- HMMA GEMM ----------------
// C[M,N] = sum_k A[m,k]*B[n,k]  (both K-major), split-precision products.
// MODE 0: A=Ut hi/lo, B=qbf (exact).   epi: v*dq_mul - dq_sub*colsum[row]; emit hi/lo -> g_T1
// MODE 1: A=T1 hi/lo, B=Vt hi/lo.      epi: v / scaleWH[col];              emit hi/lo -> g_W
// MODE 2: A=x  hi/lo, B=W  hi/lo.      epi: v + bias[col];                 emit fp32 -> out
constexpr int BM = 128, BN = 256, BK = 64, NCHUNK = KDIM / BK;
constexpr uint32_t TILE_A = 128 * 128;   // 16 KB per split
constexpr uint32_t TILE_B = 256 * 128;   // 32 KB per split
constexpr uint32_t OFF_AH = 0, OFF_AL = TILE_A, OFF_BH = 2 * TILE_A;
constexpr uint32_t OFF_BL = 2 * TILE_A + TILE_B;

template <int MODE>
__global__ __launch_bounds__(512, 1) void hgemm(const float* __restrict__ aux,
                                                float* __restrict__ outp) {
    constexpr bool HAS_BL = (MODE != 0);
    constexpr uint32_t ST = HAS_BL ? (2 * TILE_A + 2 * TILE_B) : (2 * TILE_A + TILE_B);
    constexpr int WM = (MODE == 0) ? 32 : 64;   // warp tile rows
    constexpr int WN = (MODE == 0) ? 64 : 32;   // warp tile cols
    constexpr int MT = WM / 16, NT = WN / 8;

    const bf16 *Ahi, *Alo, *Bhi, *Blo = nullptr;
    if (MODE == 0) { Ahi = g_Ut_hi; Alo = g_Ut_lo; Bhi = g_qbf; }
    if (MODE == 1) { Ahi = g_T1_hi; Alo = g_T1_lo; Bhi = g_Vt_hi; Blo = g_Vt_lo; }
    if (MODE == 2) { Ahi = g_x_hi;  Alo = g_x_lo;  Bhi = g_W_hi;  Blo = g_W_lo; }

    extern __shared__ char dsm[];
    const uint32_t sbase = (smem_u32(dsm) + 1023u) & ~1023u;

    const int tid = threadIdx.x;
    const int wid = tid >> 5, lane = tid & 31;
    const int warp_m = (MODE == 0) ? (wid >> 2) : (wid >> 3);
    const int warp_n = (MODE == 0) ? (wid & 3) : (wid & 7);
    const int m0 = blockIdx.y * BM, n0 = blockIdx.x * BN;

    float acc[MT][NT][4];
#pragma unroll
    for (int a = 0; a < MT; a++)
#pragma unroll
        for (int b = 0; b < NT; b++)
#pragma unroll
            for (int d = 0; d < 4; d++) acc[a][b][d] = 0.f;

    auto load_stage = [&](int s, int c) {
        const uint32_t sb = sbase + (uint32_t)s * ST;
        const int k0 = c * BK;
#pragma unroll
        for (int t = 0; t < 2; t++) {          // A: 128 rows x 8 c16 = 1024 slots
            int idx = tid + t * 512;
            int r = idx >> 3, cc = idx & 7;
            uint32_t sw = sw128((uint32_t)(r * 128 + cc * 16));
            size_t g = (size_t)(m0 + r) * KDIM + k0 + cc * 8;
            cp16(sb + OFF_AH + sw, Ahi + g);
            cp16(sb + OFF_AL + sw, Alo + g);
        }
#pragma unroll
        for (int t = 0; t < 4; t++) {          // B: 256 rows x 8 c16 = 2048 slots
            int idx = tid + t * 512;
            int r = idx >> 3, cc = idx & 7;
            uint32_t sw = sw128((uint32_t)(r * 128 + cc * 16));
            size_t g = (size_t)(n0 + r) * KDIM + k0 + cc * 8;
            cp16(sb + OFF_BH + sw, Bhi + g);
            if (HAS_BL) cp16(sb + OFF_BL + sw, Blo + g);
        }
        asm volatile("cp.async.commit_group;");
    };

    load_stage(0, 0);

    const uint32_t a_row = (uint32_t)(warp_m * WM + (lane & 15));
    const uint32_t a_kb  = (uint32_t)((lane >> 4) << 4);
    const uint32_t b_row = (uint32_t)(warp_n * WN + ((lane >> 4) << 3) + (lane & 7));
    const uint32_t b_kb  = (uint32_t)(((lane >> 3) & 1) << 4);

    for (int c = 0; c < NCHUNK; c++) {
        asm volatile("cp.async.wait_group 0;");
        __syncthreads();
        if (c + 1 < NCHUNK) load_stage((c + 1) & 1, c + 1);

        const uint32_t sb = sbase + (uint32_t)(c & 1) * ST;
#pragma unroll
        for (int ks = 0; ks < BK / 16; ks++) {
            uint32_t ah[MT][4], al[MT][4], bh[NT][2], bl[NT][2];
#pragma unroll
            for (int mt = 0; mt < MT; mt++) {
                uint32_t o = sw128((a_row + mt * 16) * 128 + ks * 32 + a_kb);
                ldsm4(ah[mt], sb + OFF_AH + o);
                ldsm4(al[mt], sb + OFF_AL + o);
            }
#pragma unroll
            for (int np = 0; np < NT / 2; np++) {
                uint32_t o = sw128((b_row + np * 16) * 128 + ks * 32 + b_kb);
                uint32_t tmp[4];
                ldsm4(tmp, sb + OFF_BH + o);
                bh[2 * np][0] = tmp[0]; bh[2 * np][1] = tmp[1];
                bh[2 * np + 1][0] = tmp[2]; bh[2 * np + 1][1] = tmp[3];
                if (HAS_BL) {
                    ldsm4(tmp, sb + OFF_BL + o);
                    bl[2 * np][0] = tmp[0]; bl[2 * np][1] = tmp[1];
                    bl[2 * np + 1][0] = tmp[2]; bl[2 * np + 1][1] = tmp[3];
                }
            }
#pragma unroll
            for (int mt = 0; mt < MT; mt++)
#pragma unroll
                for (int nt = 0; nt < NT; nt++) {
                    mma16816(acc[mt][nt], ah[mt], bh[nt]);
                    if (HAS_BL) mma16816(acc[mt][nt], ah[mt], bl[nt]);
                    mma16816(acc[mt][nt], al[mt], bh[nt]);
                }
        }
    }

    // ---------------- epilogue ----------------
    const int gid = lane >> 2, tig = lane & 3;
    float dq_mul = 0.f, dq_sub = 0.f;
    if (MODE == 0) { float sc = aux[0]; dq_mul = sc * (2.0f / 15.0f); dq_sub = sc; }

    float c0f[NT], c1f[NT];
#pragma unroll
    for (int nt = 0; nt < NT; nt++) {
        int col = n0 + warp_n * WN + nt * 8 + tig * 2;
        if (MODE == 1) { c0f[nt] = 1.0f / aux[col]; c1f[nt] = 1.0f / aux[col + 1]; }
        else if (MODE == 2) { c0f[nt] = aux[col]; c1f[nt] = aux[col + 1]; }
        else { c0f[nt] = 0.f; c1f[nt] = 0.f; }
    }

#pragma unroll
    for (int mt = 0; mt < MT; mt++) {
        int r0 = m0 + warp_m * WM + mt * 16 + gid;
        int r1 = r0 + 8;
        float sub0 = 0.f, sub1 = 0.f;
        if (MODE == 0) {
            float cs0 = 0.f, cs1 = 0.f;
#pragma unroll
            for (int p = 0; p < 8; p++) {
                cs0 += g_cs_part[p * 4096 + r0];
                cs1 += g_cs_part[p * 4096 + r1];
            }
            sub0 = dq_sub * cs0; sub1 = dq_sub * cs1;
        }
#pragma unroll
        for (int nt = 0; nt < NT; nt++) {
            int col = n0 + warp_n * WN + nt * 8 + tig * 2;
            float v0 = acc[mt][nt][0], v1 = acc[mt][nt][1];
            float v2 = acc[mt][nt][2], v3 = acc[mt][nt][3];
            if (MODE == 0) {
                v0 = v0 * dq_mul - sub0; v1 = v1 * dq_mul - sub0;
                v2 = v2 * dq_mul - sub1; v3 = v3 * dq_mul - sub1;
            } else if (MODE == 1) {
                v0 *= c0f[nt]; v1 *= c1f[nt]; v2 *= c0f[nt]; v3 *= c1f[nt];
            } else {
                v0 += c0f[nt]; v1 += c1f[nt]; v2 += c0f[nt]; v3 += c1f[nt];
            }
            if (MODE == 2) {
                *(float2*)(outp + (size_t)r0 * 4096 + col) = make_float2(v0, v1);
                *(float2*)(outp + (size_t)r1 * 4096 + col) = make_float2(v2, v3);
            } else {
                bf16* Chi = (MODE == 0) ? g_T1_hi : g_W_hi;
                bf16* Clo = (MODE == 0) ? g_T1_lo : g_W_lo;
                union { bf16 b[2]; uint32_t u; } h, l;
                h.b[0] = __float2bfloat16(v0);
                l.b[0] = __float2bfloat16(v0 - __bfloat162float(h.b[0]));
                h.b[1] = __float2bfloat16(v1);
                l.b[1] = __float2bfloat16(v1 - __bfloat162float(h.b[1]));
                *(uint32_t*)(Chi + (size_t)r0 * 4096 + col) = h.u;
                *(uint32_t*)(Clo + (size_t)r0 * 4096 + col) = l.u;
                h.b[0] = __float2bfloat16(v2);
                l.b[0] = __float2bfloat16(v2 - __bfloat162float(h.b[0]));
                h.b[1] = __float2bfloat16(v3);
                l.b[1] = __float2bfloat16(v3 - __bfloat162float(h.b[1]));
                *(uint32_t*)(Chi + (size_t)r1 * 4096 + col) = h.u;
                *(uint32_t*)(Clo + (size_t)r1 * 4096 + col) = l.u;
            }
        }
    }
}

// ---------------- host ----------------
extern "C" void kernel_launch(void* const* d_in, const int* in_sizes, int n_in,
                              void* d_out, int out_size) {
    const float* x       = (const float*)d_in[0];
    const int*   qweight = (const int*)  d_in[1];
    const float* scale   = (const float*)d_in[2];
    const float* scaleWH = (const float*)d_in[3];
    const float* bias    = (const float*)d_in[4];
    const float* U       = (const float*)d_in[5];
    const float* V       = (const float*)d_in[6];
    float*       out     = (float*)d_out;

    constexpr uint32_t SM0 = 2 * (2 * TILE_A + TILE_B) + 1024;       // 129 KB
    constexpr uint32_t SM12 = 2 * (2 * TILE_A + 2 * TILE_B) + 1024;  // 193 KB
    cudaFuncSetAttribute(hgemm<0>, cudaFuncAttributeMaxDynamicSharedMemorySize, SM0);
    cudaFuncSetAttribute(hgemm<1>, cudaFuncAttributeMaxDynamicSharedMemorySize, SM12);
    cudaFuncSetAttribute(hgemm<2>, cudaFuncAttributeMaxDynamicSharedMemorySize, SM12);

    dim3 tb32(32, 8);
    colsum_part<<<dim3(16, 8), 256>>>(U);                         // 0
    transconv<0><<<dim3(128, 128), tb32>>>(U);                    // 1
    convq<<<16384, 256>>>(qweight);                               // 2
    hgemm<0><<<dim3(16, 32), 512, SM0>>>(scale, nullptr);         // 3 <- profiled
    transconv<1><<<dim3(128, 128), tb32>>>(V);                    // 4
    hgemm<1><<<dim3(16, 32), 512, SM12>>>(scaleWH, nullptr);      // 5
    convx<<<(unsigned)(SZ_X / 4 / 256), 256>>>(x);                // 6
    hgemm<2><<<dim3(16, 64), 512, SM12>>>(bias, out);             // 7
}

// round 6
// speedup vs baseline: 1.1866x; 1.0027x over previous
#include <cuda_runtime.h>
#include <cuda_bf16.h>
#include <cstdint>

using bf16 = __nv_bfloat16;

constexpr int KDIM = 4096;
constexpr size_t SZ_W = (size_t)4096 * 4096;
constexpr size_t SZ_X = (size_t)8192 * 4096;

// ---------------- static device scratch ----------------
__device__ bf16 g_Ut_hi[SZ_W], g_Ut_lo[SZ_W];   // Ut[o,a] = U[a,o]
__device__ bf16 g_Vt_hi[SZ_W], g_Vt_lo[SZ_W];   // Vt[i,b] = V[b,i]
__device__ bf16 g_qbf[SZ_W];                    // q[b,a] as bf16 (exact)
__device__ bf16 g_x_hi[SZ_X], g_x_lo[SZ_X];     // x[m,i]
__device__ bf16 g_T1_hi[SZ_W], g_T1_lo[SZ_W];   // T[o,b] hi/lo
__device__ bf16 g_W_hi[SZ_W],  g_W_lo[SZ_W];    // Wtt[o,i] hi/lo
__device__ float g_cs_part[8 * 4096];           // partial colsums of U

// ---------------- PTX helpers ----------------
__device__ __forceinline__ uint32_t smem_u32(const void* p) {
    uint32_t a;
    asm("{ .reg .u64 t; cvta.to.shared.u64 t, %1; cvt.u32.u64 %0, t; }" : "=r"(a) : "l"(p));
    return a;
}
__device__ __forceinline__ void cp16(uint32_t dst, const void* src) {
    asm volatile("cp.async.cg.shared.global [%0], [%1], 16;" :: "r"(dst), "l"(src));
}
__device__ __forceinline__ void ldsm4(uint32_t* r, uint32_t addr) {
    asm volatile("ldmatrix.sync.aligned.m8n8.x4.shared.b16 {%0,%1,%2,%3}, [%4];"
                 : "=r"(r[0]), "=r"(r[1]), "=r"(r[2]), "=r"(r[3]) : "r"(addr));
}
__device__ __forceinline__ void mma16816(float* c, const uint32_t* a, const uint32_t* b) {
    asm volatile("mma.sync.aligned.m16n8k16.row.col.f32.bf16.bf16.f32 "
                 "{%0,%1,%2,%3}, {%4,%5,%6,%7}, {%8,%9}, {%0,%1,%2,%3};"
                 : "+f"(c[0]), "+f"(c[1]), "+f"(c[2]), "+f"(c[3])
                 : "r"(a[0]), "r"(a[1]), "r"(a[2]), "r"(a[3]), "r"(b[0]), "r"(b[1]));
}
__device__ __forceinline__ uint32_t sw128(uint32_t o) { return o ^ ((o >> 3) & 0x70); }

// ---------------- preprocessing ----------------
template <int WHICH>
__global__ void transconv(const float* __restrict__ src) {
    bf16* dhi = (WHICH == 0) ? g_Ut_hi : g_Vt_hi;
    bf16* dlo = (WHICH == 0) ? g_Ut_lo : g_Vt_lo;
    __shared__ float t[32][33];
    int c0 = blockIdx.x * 32, r0 = blockIdx.y * 32;
    int tx = threadIdx.x, ty = threadIdx.y;
#pragma unroll
    for (int j = 0; j < 4; j++)
        t[ty + j * 8][tx] = src[(size_t)(r0 + ty + j * 8) * 4096 + c0 + tx];
    __syncthreads();
#pragma unroll
    for (int j = 0; j < 4; j++) {
        int c = c0 + ty + j * 8;
        float v = t[tx][ty + j * 8];
        bf16 h = __float2bfloat16(v);
        dhi[(size_t)c * 4096 + r0 + tx] = h;
        dlo[(size_t)c * 4096 + r0 + tx] = __float2bfloat16(v - __bfloat162float(h));
    }
}

__global__ void convx(const float* __restrict__ xin) {
    size_t i = (size_t)blockIdx.x * 256 + threadIdx.x;
    float4 v = ((const float4*)xin)[i];
    union { bf16 b[4]; uint2 u; } H, L;
    float f[4] = {v.x, v.y, v.z, v.w};
#pragma unroll
    for (int j = 0; j < 4; j++) {
        bf16 h = __float2bfloat16(f[j]);
        H.b[j] = h;
        L.b[j] = __float2bfloat16(f[j] - __bfloat162float(h));
    }
    ((uint2*)g_x_hi)[i] = H.u;
    ((uint2*)g_x_lo)[i] = L.u;
}

__global__ void convq(const int* __restrict__ q) {
    size_t i = (size_t)blockIdx.x * 256 + threadIdx.x;
    int4 v = ((const int4*)q)[i];
    union { bf16 b[4]; uint2 u; } H;
    H.b[0] = __float2bfloat16((float)v.x);
    H.b[1] = __float2bfloat16((float)v.y);
    H.b[2] = __float2bfloat16((float)v.z);
    H.b[3] = __float2bfloat16((float)v.w);
    ((uint2*)g_qbf)[i] = H.u;
}

__global__ void colsum_part(const float* __restrict__ U) {
    int col = blockIdx.x * 256 + threadIdx.x;
    int seg = blockIdx.y;
    float s = 0.f;
    for (int k = seg * 512; k < seg * 512 + 512; k++)
        s += U[(size_t)k * 4096 + col];
    g_cs_part[seg * 4096 + col] = s;
}

// ---------------- HMMA GEMM ----------------
// C[M,N] = sum_k A[m,k]*B[n,k] (both K-major), split-precision products.
// 256 threads, 8 warps in 2x4 grid, warp tile 64x64, CTA tile 128x256, BK=64.
constexpr int BM = 128, BN = 256, BK = 64, NCHUNK = KDIM / BK;
constexpr uint32_t TILE_A = 128 * 128;   // 16 KB per split
constexpr uint32_t TILE_B = 256 * 128;   // 32 KB per split
constexpr uint32_t OFF_AH = 0, OFF_AL = TILE_A, OFF_BH = 2 * TILE_A;
constexpr uint32_t OFF_BL = 2 * TILE_A + TILE_B;
constexpr int WM = 64, WN = 64, MT = WM / 16, NT = WN / 8;

template <int MODE>
__global__ __launch_bounds__(256, 1) void hgemm(const float* __restrict__ aux,
                                                float* __restrict__ outp) {
    constexpr bool HAS_BL = (MODE != 0);
    constexpr uint32_t ST = HAS_BL ? (2 * TILE_A + 2 * TILE_B) : (2 * TILE_A + TILE_B);

    const bf16 *Ahi, *Alo, *Bhi, *Blo = nullptr;
    if (MODE == 0) { Ahi = g_Ut_hi; Alo = g_Ut_lo; Bhi = g_qbf; }
    if (MODE == 1) { Ahi = g_T1_hi; Alo = g_T1_lo; Bhi = g_Vt_hi; Blo = g_Vt_lo; }
    if (MODE == 2) { Ahi = g_x_hi;  Alo = g_x_lo;  Bhi = g_W_hi;  Blo = g_W_lo; }

    extern __shared__ char dsm[];
    const uint32_t sbase = (smem_u32(dsm) + 1023u) & ~1023u;

    const int tid = threadIdx.x;
    const int wid = tid >> 5, lane = tid & 31;
    const int warp_m = wid >> 2;   // 0..1
    const int warp_n = wid & 3;    // 0..3
    const int m0 = blockIdx.y * BM, n0 = blockIdx.x * BN;

    float acc[MT][NT][4];
#pragma unroll
    for (int a = 0; a < MT; a++)
#pragma unroll
        for (int b = 0; b < NT; b++)
#pragma unroll
            for (int d = 0; d < 4; d++) acc[a][b][d] = 0.f;

    auto load_stage = [&](int s, int c) {
        const uint32_t sb = sbase + (uint32_t)s * ST;
        const int k0 = c * BK;
#pragma unroll
        for (int t = 0; t < 4; t++) {          // A: 1024 slots per split
            int idx = tid + t * 256;
            int r = idx >> 3, cc = idx & 7;
            uint32_t sw = sw128((uint32_t)(r * 128 + cc * 16));
            size_t g = (size_t)(m0 + r) * KDIM + k0 + cc * 8;
            cp16(sb + OFF_AH + sw, Ahi + g);
            cp16(sb + OFF_AL + sw, Alo + g);
        }
#pragma unroll
        for (int t = 0; t < 8; t++) {          // B: 2048 slots per split
            int idx = tid + t * 256;
            int r = idx >> 3, cc = idx & 7;
            uint32_t sw = sw128((uint32_t)(r * 128 + cc * 16));
            size_t g = (size_t)(n0 + r) * KDIM + k0 + cc * 8;
            cp16(sb + OFF_BH + sw, Bhi + g);
            if (HAS_BL) cp16(sb + OFF_BL + sw, Blo + g);
        }
        asm volatile("cp.async.commit_group;");
    };

    load_stage(0, 0);

    const uint32_t a_row = (uint32_t)(warp_m * WM + (lane & 15));
    const uint32_t a_kb  = (uint32_t)((lane >> 4) << 4);
    const uint32_t b_row = (uint32_t)(warp_n * WN + ((lane >> 4) << 3) + (lane & 7));
    const uint32_t b_kb  = (uint32_t)(((lane >> 3) & 1) << 4);

    for (int c = 0; c < NCHUNK; c++) {
        asm volatile("cp.async.wait_group 0;");
        __syncthreads();
        if (c + 1 < NCHUNK) load_stage((c + 1) & 1, c + 1);

        const uint32_t sb = sbase + (uint32_t)(c & 1) * ST;
#pragma unroll
        for (int ks = 0; ks < BK / 16; ks++) {
            uint32_t ah[MT][4], al[MT][4], bh[NT][2], bl[NT][2];
#pragma unroll
            for (int mt = 0; mt < MT; mt++) {
                uint32_t o = sw128((a_row + mt * 16) * 128 + ks * 32 + a_kb);
                ldsm4(ah[mt], sb + OFF_AH + o);
                ldsm4(al[mt], sb + OFF_AL + o);
            }
#pragma unroll
            for (int np = 0; np < NT / 2; np++) {
                uint32_t o = sw128((b_row + np * 16) * 128 + ks * 32 + b_kb);
                uint32_t tmp[4];
                ldsm4(tmp, sb + OFF_BH + o);
                bh[2 * np][0] = tmp[0]; bh[2 * np][1] = tmp[1];
                bh[2 * np + 1][0] = tmp[2]; bh[2 * np + 1][1] = tmp[3];
                if (HAS_BL) {
                    ldsm4(tmp, sb + OFF_BL + o);
                    bl[2 * np][0] = tmp[0]; bl[2 * np][1] = tmp[1];
                    bl[2 * np + 1][0] = tmp[2]; bl[2 * np + 1][1] = tmp[3];
                }
            }
#pragma unroll
            for (int mt = 0; mt < MT; mt++)
#pragma unroll
                for (int nt = 0; nt < NT; nt++) {
                    mma16816(acc[mt][nt], ah[mt], bh[nt]);
                    if (HAS_BL) mma16816(acc[mt][nt], ah[mt], bl[nt]);
                    mma16816(acc[mt][nt], al[mt], bh[nt]);
                }
        }
    }

    // ---------------- epilogue ----------------
    const int gid = lane >> 2, tig = lane & 3;
    float dq_mul = 0.f, dq_sub = 0.f;
    if (MODE == 0) { float sc = aux[0]; dq_mul = sc * (2.0f / 15.0f); dq_sub = sc; }

    float c0f[NT], c1f[NT];
#pragma unroll
    for (int nt = 0; nt < NT; nt++) {
        int col = n0 + warp_n * WN + nt * 8 + tig * 2;
        if (MODE == 1) { c0f[nt] = 1.0f / aux[col]; c1f[nt] = 1.0f / aux[col + 1]; }
        else if (MODE == 2) { c0f[nt] = aux[col]; c1f[nt] = aux[col + 1]; }
        else { c0f[nt] = 0.f; c1f[nt] = 0.f; }
    }

#pragma unroll
    for (int mt = 0; mt < MT; mt++) {
        int r0 = m0 + warp_m * WM + mt * 16 + gid;
        int r1 = r0 + 8;
        float sub0 = 0.f, sub1 = 0.f;
        if (MODE == 0) {
            float cs0 = 0.f, cs1 = 0.f;
#pragma unroll
            for (int p = 0; p < 8; p++) {
                cs0 += g_cs_part[p * 4096 + r0];
                cs1 += g_cs_part[p * 4096 + r1];
            }
            sub0 = dq_sub * cs0; sub1 = dq_sub * cs1;
        }
#pragma unroll
        for (int nt = 0; nt < NT; nt++) {
            int col = n0 + warp_n * WN + nt * 8 + tig * 2;
            float v0 = acc[mt][nt][0], v1 = acc[mt][nt][1];
            float v2 = acc[mt][nt][2], v3 = acc[mt][nt][3];
            if (MODE == 0) {
                v0 = v0 * dq_mul - sub0; v1 = v1 * dq_mul - sub0;
                v2 = v2 * dq_mul - sub1; v3 = v3 * dq_mul - sub1;
            } else if (MODE == 1) {
                v0 *= c0f[nt]; v1 *= c1f[nt]; v2 *= c0f[nt]; v3 *= c1f[nt];
            } else {
                v0 += c0f[nt]; v1 += c1f[nt]; v2 += c0f[nt]; v3 += c1f[nt];
            }
            if (MODE == 2) {
                *(float2*)(outp + (size_t)r0 * 4096 + col) = make_float2(v0, v1);
                *(float2*)(outp + (size_t)r1 * 4096 + col) = make_float2(v2, v3);
            } else {
                bf16* Chi = (MODE == 0) ? g_T1_hi : g_W_hi;
                bf16* Clo = (MODE == 0) ? g_T1_lo : g_W_lo;
                union { bf16 b[2]; uint32_t u; } h, l;
                h.b[0] = __float2bfloat16(v0);
                l.b[0] = __float2bfloat16(v0 - __bfloat162float(h.b[0]));
                h.b[1] = __float2bfloat16(v1);
                l.b[1] = __float2bfloat16(v1 - __bfloat162float(h.b[1]));
                *(uint32_t*)(Chi + (size_t)r0 * 4096 + col) = h.u;
                *(uint32_t*)(Clo + (size_t)r0 * 4096 + col) = l.u;
                h.b[0] = __float2bfloat16(v2);
                l.b[0] = __float2bfloat16(v2 - __bfloat162float(h.b[0]));
                h.b[1] = __float2bfloat16(v3);
                l.b[1] = __float2bfloat16(v3 - __bfloat162float(h.b[1]));
                *(uint32_t*)(Chi + (size_t)r1 * 4096 + col) = h.u;
                *(uint32_t*)(Clo + (size_t)r1 * 4096 + col) = l.u;
            }
        }
    }
}

// ---------------- host ----------------
extern "C" void kernel_launch(void* const* d_in, const int* in_sizes, int n_in,
                              void* d_out, int out_size) {
    const float* x       = (const float*)d_in[0];
    const int*   qweight = (const int*)  d_in[1];
    const float* scale   = (const float*)d_in[2];
    const float* scaleWH = (const float*)d_in[3];
    const float* bias    = (const float*)d_in[4];
    const float* U       = (const float*)d_in[5];
    const float* V       = (const float*)d_in[6];
    float*       out     = (float*)d_out;

    constexpr uint32_t SM0 = 2 * (2 * TILE_A + TILE_B) + 1024;
    constexpr uint32_t SM12 = 2 * (2 * TILE_A + 2 * TILE_B) + 1024;
    cudaFuncSetAttribute(hgemm<0>, cudaFuncAttributeMaxDynamicSharedMemorySize, SM0);
    cudaFuncSetAttribute(hgemm<1>, cudaFuncAttributeMaxDynamicSharedMemorySize, SM12);
    cudaFuncSetAttribute(hgemm<2>, cudaFuncAttributeMaxDynamicSharedMemorySize, SM12);

    dim3 tb32(32, 8);
    colsum_part<<<dim3(16, 8), 256>>>(U);                         // 0
    transconv<0><<<dim3(128, 128), tb32>>>(U);                    // 1
    convq<<<16384, 256>>>(qweight);                               // 2
    hgemm<0><<<dim3(16, 32), 256, SM0>>>(scale, nullptr);         // 3 <- profiled
    transconv<1><<<dim3(128, 128), tb32>>>(V);                    // 4
    hgemm<1><<<dim3(16, 32), 256, SM12>>>(scaleWH, nullptr);      // 5
    convx<<<(unsigned)(SZ_X / 4 / 256), 256>>>(x);                // 6
    hgemm<2><<<dim3(16, 64), 256, SM12>>>(bias, out);             // 7
}